// round 1
// baseline (speedup 1.0000x reference)
#include <cuda_runtime.h>
#include <math.h>

// Problem constants (fixed shapes from reference)
#define NE      8       // experts
#define TOPK    2
#define HID     1024
#define INTERN  4096
#define TTOK    8192    // S*B
#define CAP     2560    // ceil(T*K*1.25/E) = 2560 (exact)
#define ECAP    (NE*CAP) // 20480

// Scratch (static device globals; no runtime allocation allowed)
__device__ int   g_src_token[ECAP];                    // token feeding each expert slot, -1 = empty
__device__ int   g_slot[TTOK * TOPK];                  // slot per (t,k); ECAP = dropped
__device__ float g_inter[(size_t)ECAP * INTERN];       // silu(gate)*up, (E,C,I)  ~336MB
__device__ float g_eo[(size_t)ECAP * HID];             // expert output, (E,C,H)  ~84MB

// ---------------------------------------------------------------------------
// Routing: per-expert sequential position (cumsum order = token order),
// capacity drop at CAP. One warp per expert, warp-ballot prefix scan.
// ---------------------------------------------------------------------------
__global__ void routing_kernel(const int* __restrict__ expert_index) {
    const int e    = threadIdx.x >> 5;   // expert id = warp id (8 warps)
    const int lane = threadIdx.x & 31;
    int count = 0;
    for (int base = 0; base < TTOK; base += 32) {
        const int t = base + lane;
        const int2 ei = ((const int2*)expert_index)[t];
        int k = -1;
        if (ei.x == e) k = 0;
        else if (ei.y == e) k = 1;
        const unsigned m = __ballot_sync(0xffffffffu, k >= 0);
        if (k >= 0) {
            const int pos = count + __popc(m & ((1u << lane) - 1u));
            if (pos < CAP) {
                g_src_token[e * CAP + pos] = t;
                g_slot[t * TOPK + k] = e * CAP + pos;
            } else {
                g_slot[t * TOPK + k] = ECAP;  // dropped
            }
        }
        count += __popc(m);
    }
    // mark unused slots empty (A rows read as zero)
    const int filled = count < CAP ? count : CAP;
    for (int p = filled + lane; p < CAP; p += 32)
        g_src_token[e * CAP + p] = -1;
}

// ---------------------------------------------------------------------------
// GEMM1 fused with SiLU gating.
// Block computes a 128x64 tile of intermediate[e] = silu(A@Bg) * (A@Bu),
// A rows gathered from hidden_states via g_src_token (dispatch fused here).
// BM=128, BN=64 (x2 for gate/up), BK=16, 256 threads, 8x(4+4) per thread.
// ---------------------------------------------------------------------------
__global__ __launch_bounds__(256) void gemm1_silu(
        const float* __restrict__ x, const float* __restrict__ gup) {
    __shared__ float As[16][128];
    __shared__ float Bg[16][64];
    __shared__ float Bu[16][64];

    const int e    = blockIdx.z;
    const int row0 = blockIdx.y * 128;
    const int n0   = blockIdx.x * 64;
    const float* B = gup + (size_t)e * HID * (2 * INTERN);

    const int tid  = threadIdx.x;
    const int r0   = tid >> 2;            // 0..63 (A load row)
    const int quad = (tid & 3) * 4;       // 0,4,8,12 (A load k-offset)
    const int s0   = g_src_token[e * CAP + row0 + r0];
    const int s1   = g_src_token[e * CAP + row0 + r0 + 64];
    const int bk   = tid >> 4;            // 0..15 (B load k-row)
    const int bf   = (tid & 15) * 4;      // B load col
    const int tx   = tid & 15;            // 4 output cols (per half)
    const int ty   = tid >> 4;            // 8 output rows

    float accg[8][4], accu[8][4];
#pragma unroll
    for (int i = 0; i < 8; i++)
#pragma unroll
        for (int j = 0; j < 4; j++) { accg[i][j] = 0.f; accu[i][j] = 0.f; }

    for (int k0 = 0; k0 < HID; k0 += 16) {
        float4 a0 = make_float4(0.f, 0.f, 0.f, 0.f);
        float4 a1 = make_float4(0.f, 0.f, 0.f, 0.f);
        if (s0 >= 0) a0 = *(const float4*)(x + (size_t)s0 * HID + k0 + quad);
        if (s1 >= 0) a1 = *(const float4*)(x + (size_t)s1 * HID + k0 + quad);
        const float* brow = B + (size_t)(k0 + bk) * (2 * INTERN) + n0;
        const float4 bgv = *(const float4*)(brow + bf);
        const float4 buv = *(const float4*)(brow + INTERN + bf);

        __syncthreads();
        As[quad + 0][r0] = a0.x; As[quad + 1][r0] = a0.y;
        As[quad + 2][r0] = a0.z; As[quad + 3][r0] = a0.w;
        As[quad + 0][r0 + 64] = a1.x; As[quad + 1][r0 + 64] = a1.y;
        As[quad + 2][r0 + 64] = a1.z; As[quad + 3][r0 + 64] = a1.w;
        *(float4*)&Bg[bk][bf] = bgv;
        *(float4*)&Bu[bk][bf] = buv;
        __syncthreads();

#pragma unroll
        for (int kk = 0; kk < 16; kk++) {
            float a[8];
            *(float4*)(a)     = *(const float4*)&As[kk][ty * 8];
            *(float4*)(a + 4) = *(const float4*)&As[kk][ty * 8 + 4];
            const float4 bg = *(const float4*)&Bg[kk][tx * 4];
            const float4 bu = *(const float4*)&Bu[kk][tx * 4];
#pragma unroll
            for (int i = 0; i < 8; i++) {
                accg[i][0] += a[i] * bg.x; accg[i][1] += a[i] * bg.y;
                accg[i][2] += a[i] * bg.z; accg[i][3] += a[i] * bg.w;
                accu[i][0] += a[i] * bu.x; accu[i][1] += a[i] * bu.y;
                accu[i][2] += a[i] * bu.z; accu[i][3] += a[i] * bu.w;
            }
        }
    }

#pragma unroll
    for (int i = 0; i < 8; i++) {
        float4 o;
        float* op = &o.x;
#pragma unroll
        for (int j = 0; j < 4; j++) {
            const float g = accg[i][j];
            const float u = accu[i][j];
            op[j] = (g / (1.f + expf(-g))) * u;
        }
        const size_t orow = ((size_t)e * CAP + row0 + ty * 8 + i) * INTERN + n0 + tx * 4;
        *(float4*)(g_inter + orow) = o;
    }
}

// ---------------------------------------------------------------------------
// GEMM2: expert_out[e] = inter[e] @ down_proj[e].  BM=128, BN=128, BK=16.
// ---------------------------------------------------------------------------
__global__ __launch_bounds__(256) void gemm2(const float* __restrict__ dp) {
    __shared__ float As[16][128];
    __shared__ float Bs[16][128];

    const int e    = blockIdx.z;
    const int row0 = blockIdx.y * 128;
    const int n0   = blockIdx.x * 128;
    const float* B = dp + (size_t)e * INTERN * HID;

    const int tid  = threadIdx.x;
    const int r0   = tid >> 2;
    const int quad = (tid & 3) * 4;
    const float* Ar0 = g_inter + ((size_t)e * CAP + row0 + r0) * INTERN;
    const float* Ar1 = g_inter + ((size_t)e * CAP + row0 + r0 + 64) * INTERN;
    const int bk = tid >> 4;
    const int bf = (tid & 15) * 4;
    const int tx = tid & 15;
    const int ty = tid >> 4;

    float acc[8][8];
#pragma unroll
    for (int i = 0; i < 8; i++)
#pragma unroll
        for (int j = 0; j < 8; j++) acc[i][j] = 0.f;

    for (int k0 = 0; k0 < INTERN; k0 += 16) {
        const float4 a0 = *(const float4*)(Ar0 + k0 + quad);
        const float4 a1 = *(const float4*)(Ar1 + k0 + quad);
        const float* brow = B + (size_t)(k0 + bk) * HID + n0;
        const float4 b0 = *(const float4*)(brow + bf);
        const float4 b1 = *(const float4*)(brow + bf + 64);

        __syncthreads();
        As[quad + 0][r0] = a0.x; As[quad + 1][r0] = a0.y;
        As[quad + 2][r0] = a0.z; As[quad + 3][r0] = a0.w;
        As[quad + 0][r0 + 64] = a1.x; As[quad + 1][r0 + 64] = a1.y;
        As[quad + 2][r0 + 64] = a1.z; As[quad + 3][r0 + 64] = a1.w;
        *(float4*)&Bs[bk][bf]      = b0;
        *(float4*)&Bs[bk][bf + 64] = b1;
        __syncthreads();

#pragma unroll
        for (int kk = 0; kk < 16; kk++) {
            float a[8], b[8];
            *(float4*)(a)     = *(const float4*)&As[kk][ty * 8];
            *(float4*)(a + 4) = *(const float4*)&As[kk][ty * 8 + 4];
            *(float4*)(b)     = *(const float4*)&Bs[kk][tx * 8];
            *(float4*)(b + 4) = *(const float4*)&Bs[kk][tx * 8 + 4];
#pragma unroll
            for (int i = 0; i < 8; i++)
#pragma unroll
                for (int j = 0; j < 8; j++)
                    acc[i][j] += a[i] * b[j];
        }
    }

#pragma unroll
    for (int i = 0; i < 8; i++) {
        const size_t orow = ((size_t)e * CAP + row0 + ty * 8 + i) * HID + n0 + tx * 8;
        float4 o0, o1;
        o0.x = acc[i][0]; o0.y = acc[i][1]; o0.z = acc[i][2]; o0.w = acc[i][3];
        o1.x = acc[i][4]; o1.y = acc[i][5]; o1.z = acc[i][6]; o1.w = acc[i][7];
        *(float4*)(g_eo + orow)     = o0;
        *(float4*)(g_eo + orow + 4) = o1;
    }
}

// ---------------------------------------------------------------------------
// Combine: out[t] = sum_k w[t,k] * expert_out[slot[t,k]], weights renormalized
// over top-k and zeroed for capacity-dropped assignments.
// ---------------------------------------------------------------------------
__global__ void combine_kernel(const float* __restrict__ aff,
                               const int*   __restrict__ eidx,
                               float*       __restrict__ out) {
    const int idx = blockIdx.x * 256 + threadIdx.x;   // t*256 + c4
    const int t = idx >> 8;
    const int c = (idx & 255) << 2;
    const int2 ei = ((const int2*)eidx)[t];
    const float a0 = aff[t * NE + ei.x];
    const float a1 = aff[t * NE + ei.y];
    const float inv = 1.f / (a0 + a1);
    const int s0 = g_slot[t * TOPK + 0];
    const int s1 = g_slot[t * TOPK + 1];
    float4 r = make_float4(0.f, 0.f, 0.f, 0.f);
    if (s0 < ECAP) {
        const float w = a0 * inv;
        const float4 v = *(const float4*)(g_eo + (size_t)s0 * HID + c);
        r.x += w * v.x; r.y += w * v.y; r.z += w * v.z; r.w += w * v.w;
    }
    if (s1 < ECAP) {
        const float w = a1 * inv;
        const float4 v = *(const float4*)(g_eo + (size_t)s1 * HID + c);
        r.x += w * v.x; r.y += w * v.y; r.z += w * v.z; r.w += w * v.w;
    }
    *(float4*)(out + (size_t)t * HID + c) = r;
}

// ---------------------------------------------------------------------------
extern "C" void kernel_launch(void* const* d_in, const int* in_sizes, int n_in,
                              void* d_out, int out_size) {
    const float* x    = (const float*)d_in[0];   // hidden_states (S,B,H) = (T,H)
    const float* aff  = (const float*)d_in[1];   // expert_affinities (T,E)
    const int*   eidx = (const int*)  d_in[2];   // expert_index (T,K)
    const float* gup  = (const float*)d_in[3];   // gate_up_proj (E,H,2I)
    const float* dp   = (const float*)d_in[4];   // down_proj (E,I,H)
    float* out = (float*)d_out;                  // (T,H)

    routing_kernel<<<1, 256>>>(eidx);
    gemm1_silu<<<dim3(INTERN / 64, CAP / 128, NE), 256>>>(x, gup);
    gemm2<<<dim3(HID / 128, CAP / 128, NE), 256>>>(dp);
    combine_kernel<<<dim3((TTOK * (HID / 4)) / 256), 256>>>(aff, eidx, out);
}

// round 3
// speedup vs baseline: 2.3221x; 2.3221x over previous
#include <cuda_runtime.h>
#include <cuda_bf16.h>
#include <math.h>
#include <stdint.h>

#define NE      8
#define TOPK    2
#define HID     1024
#define INTERN  4096
#define TTOK    8192
#define CAP     2560
#define ECAP    (NE*CAP)

// ---------------- scratch (static device globals) ----------------
__device__ int            g_src_token[ECAP];
__device__ int            g_slot[TTOK * TOPK];
__device__ __nv_bfloat16  g_xhi[(size_t)TTOK * HID];
__device__ __nv_bfloat16  g_xlo[(size_t)TTOK * HID];
__device__ __nv_bfloat16  g_gupT_hi[(size_t)NE * 2 * INTERN * HID];  // [e][n][k]
__device__ __nv_bfloat16  g_gupT_lo[(size_t)NE * 2 * INTERN * HID];
__device__ __nv_bfloat16  g_dpT_hi[(size_t)NE * HID * INTERN];       // [e][n][k]
__device__ __nv_bfloat16  g_dpT_lo[(size_t)NE * HID * INTERN];
__device__ __nv_bfloat16  g_inter_hi[(size_t)ECAP * INTERN];
__device__ __nv_bfloat16  g_inter_lo[(size_t)ECAP * INTERN];
__device__ float          g_eo[(size_t)ECAP * HID];

// ---------------- helpers ----------------
__device__ __forceinline__ uint32_t smem_u32(const void* p) {
    uint32_t a;
    asm("{ .reg .u64 t; cvta.to.shared.u64 t, %1; cvt.u32.u64 %0, t; }" : "=r"(a) : "l"(p));
    return a;
}
__device__ __forceinline__ void mma_bf16(float* d, const uint32_t* a, const uint32_t* b) {
    asm volatile(
        "mma.sync.aligned.m16n8k16.row.col.f32.bf16.bf16.f32 "
        "{%0,%1,%2,%3}, {%4,%5,%6,%7}, {%8,%9}, {%0,%1,%2,%3};"
        : "+f"(d[0]), "+f"(d[1]), "+f"(d[2]), "+f"(d[3])
        : "r"(a[0]), "r"(a[1]), "r"(a[2]), "r"(a[3]), "r"(b[0]), "r"(b[1]));
}
__device__ __forceinline__ void ldm4(uint32_t* r, uint32_t addr) {
    asm volatile("ldmatrix.sync.aligned.m8n8.x4.shared.b16 {%0,%1,%2,%3}, [%4];"
        : "=r"(r[0]), "=r"(r[1]), "=r"(r[2]), "=r"(r[3]) : "r"(addr));
}
__device__ __forceinline__ void cp8(uint32_t dst, const void* src, uint32_t sz) {
    asm volatile("cp.async.ca.shared.global [%0], [%1], 8, %2;"
        :: "r"(dst), "l"(src), "r"(sz) : "memory");
}
#define CP_COMMIT() asm volatile("cp.async.commit_group;" ::: "memory")
#define CP_WAIT1()  asm volatile("cp.async.wait_group 1;" ::: "memory")
#define CP_WAIT0()  asm volatile("cp.async.wait_group 0;" ::: "memory")

__device__ __forceinline__ uint32_t bpack(__nv_bfloat16 a, __nv_bfloat16 b) {
    return (uint32_t)__bfloat16_as_ushort(a) | ((uint32_t)__bfloat16_as_ushort(b) << 16);
}

// SMEM geometry: rows padded to 72 bf16 (144B). Conflict-free:
//  - ldmatrix phases: 8 rows * 36 words -> (4r mod 32) distinct 4-bank groups
//  - scalar B-frag LDS: (4n + t) mod 32 covers all 32 banks
#define ROWB   144            // bytes per padded row (72 bf16)
#define ST_SZ  73728          // bytes per pipeline stage (both gemms)
#define SM_SZ  (2 * ST_SZ)    // 147456

// ---------------------------------------------------------------------------
// Routing (verified R1)
// ---------------------------------------------------------------------------
__global__ void routing_kernel(const int* __restrict__ expert_index) {
    const int e    = threadIdx.x >> 5;
    const int lane = threadIdx.x & 31;
    int count = 0;
    for (int base = 0; base < TTOK; base += 32) {
        const int t = base + lane;
        const int2 ei = ((const int2*)expert_index)[t];
        int k = -1;
        if (ei.x == e) k = 0;
        else if (ei.y == e) k = 1;
        const unsigned m = __ballot_sync(0xffffffffu, k >= 0);
        if (k >= 0) {
            const int pos = count + __popc(m & ((1u << lane) - 1u));
            if (pos < CAP) {
                g_src_token[e * CAP + pos] = t;
                g_slot[t * TOPK + k] = e * CAP + pos;
            } else {
                g_slot[t * TOPK + k] = ECAP;
            }
        }
        count += __popc(m);
    }
    const int filled = count < CAP ? count : CAP;
    for (int p = filled + lane; p < CAP; p += 32)
        g_src_token[e * CAP + p] = -1;
}

// ---------------------------------------------------------------------------
// Prep: split hidden states to bf16 hi/lo
// ---------------------------------------------------------------------------
__global__ void split_x(const float* __restrict__ x) {
    const size_t i0 = ((size_t)blockIdx.x * 256 + threadIdx.x) * 4;
    const float4 v = *(const float4*)(x + i0);
    const float vv[4] = {v.x, v.y, v.z, v.w};
    uint32_t hp[2], lp[2];
#pragma unroll
    for (int j = 0; j < 2; j++) {
        __nv_bfloat16 h0 = __float2bfloat16(vv[2*j]);
        __nv_bfloat16 h1 = __float2bfloat16(vv[2*j+1]);
        __nv_bfloat16 l0 = __float2bfloat16(vv[2*j]   - __bfloat162float(h0));
        __nv_bfloat16 l1 = __float2bfloat16(vv[2*j+1] - __bfloat162float(h1));
        hp[j] = bpack(h0, h1);
        lp[j] = bpack(l0, l1);
    }
    *(uint2*)(g_xhi + i0) = make_uint2(hp[0], hp[1]);
    *(uint2*)(g_xlo + i0) = make_uint2(lp[0], lp[1]);
}

// ---------------------------------------------------------------------------
// Prep: transpose + bf16 hi/lo split:  in[e][R][C] -> out[e][C][R]
// ---------------------------------------------------------------------------
__device__ __forceinline__ void transpose_body(
        const float* __restrict__ in, __nv_bfloat16* __restrict__ ohi,
        __nv_bfloat16* __restrict__ olo, int R, int C) {
    __shared__ float tile[32][33];
    const int e  = blockIdx.z;
    const int r0 = blockIdx.y * 32, c0 = blockIdx.x * 32;
    const int tx = threadIdx.x & 31, ty = threadIdx.x >> 5;
    const size_t base = (size_t)e * R * C;
#pragma unroll
    for (int i = 0; i < 32; i += 8)
        tile[ty + i][tx] = in[base + (size_t)(r0 + ty + i) * C + c0 + tx];
    __syncthreads();
#pragma unroll
    for (int i = 0; i < 32; i += 8) {
        const float v = tile[tx][ty + i];
        const __nv_bfloat16 h = __float2bfloat16(v);
        const __nv_bfloat16 l = __float2bfloat16(v - __bfloat162float(h));
        const size_t o = base + (size_t)(c0 + ty + i) * R + r0 + tx;
        ohi[o] = h;
        olo[o] = l;
    }
}
__global__ void transpose_gup(const float* __restrict__ in) {
    transpose_body(in, g_gupT_hi, g_gupT_lo, HID, 2 * INTERN);
}
__global__ void transpose_dp(const float* __restrict__ in) {
    transpose_body(in, g_dpT_hi, g_dpT_lo, INTERN, HID);
}

// ---------------------------------------------------------------------------
// GEMM1: inter = silu(X@Wg)*(X@Wu), bf16 3-term split, mma.sync m16n8k16.
// CTA tile M=128, N=64(gate)+64(up), BK=64. 8 warps: 2(m) x 4(n), warp 64x16.
// SMEM stage: Ahi(0) Alo(18432) Bgh(36864) Bgl(46080) Buh(55296) Bul(64512)
// ---------------------------------------------------------------------------
__global__ __launch_bounds__(256) void gemm1_mma() {
    extern __shared__ char smem[];
    __shared__ int s_tok[128];
    const int tid  = threadIdx.x;
    const int e    = blockIdx.z;
    const int row0 = blockIdx.y * 128;
    const int n0   = blockIdx.x * 64;

    if (tid < 128) s_tok[tid] = g_src_token[e * CAP + row0 + tid];
    __syncthreads();
    const uint32_t sdyn = smem_u32(smem);

    auto load_stage = [&](int s, int buf) {
        const int k0 = s * 64;
        const uint32_t sd = sdyn + buf * ST_SZ;
#pragma unroll
        for (int i = 0; i < 8; i++) {
            const int idx = tid + i * 256, row = idx >> 4, cc = idx & 15;
            const int tok = s_tok[row];
            const int tokc = tok < 0 ? 0 : tok;
            const uint32_t sz = tok < 0 ? 0u : 8u;
            const size_t so = (size_t)tokc * HID + k0 + cc * 4;
            const uint32_t d = sd + row * ROWB + cc * 8;
            cp8(d,         g_xhi + so, sz);
            cp8(d + 18432, g_xlo + so, sz);
        }
#pragma unroll
        for (int i = 0; i < 4; i++) {
            const int idx = tid + i * 256, row = idx >> 4, cc = idx & 15;
            const size_t og = ((size_t)e * 2 * INTERN + n0 + row) * HID + k0 + cc * 4;
            const size_t ou = og + (size_t)INTERN * HID;
            const uint32_t d = sd + 36864 + row * ROWB + cc * 8;
            cp8(d,         g_gupT_hi + og, 8);
            cp8(d + 9216,  g_gupT_lo + og, 8);
            cp8(d + 18432, g_gupT_hi + ou, 8);
            cp8(d + 27648, g_gupT_lo + ou, 8);
        }
        CP_COMMIT();
    };

    const int lane = tid & 31, wid = tid >> 5;
    const int wm = (wid & 1) * 64;
    const int wn = (wid >> 1) * 16;
    const int gq = lane >> 2, tq = lane & 3;

    float accg[4][2][4] = {}, accu[4][2][4] = {};

    load_stage(0, 0);
    load_stage(1, 1);
    const int NS = HID / 64;  // 16
    for (int s = 0; s < NS; s++) {
        if (s < NS - 1) CP_WAIT1(); else CP_WAIT0();
        __syncthreads();
        const uint32_t sA = sdyn + (s & 1) * ST_SZ;
        const char*    sb = smem + (s & 1) * ST_SZ;
#pragma unroll
        for (int ks = 0; ks < 4; ks++) {
            uint32_t ah[4][4], al[4][4];
#pragma unroll
            for (int i = 0; i < 4; i++) {
                const uint32_t ad = sA + (wm + i * 16 + (lane & 15)) * ROWB
                                       + (ks * 16 + ((lane >> 4) << 3)) * 2;
                ldm4(ah[i], ad);
                ldm4(al[i], ad + 18432);
            }
            uint32_t bgh[2][2], bgl[2][2], buh[2][2], bul[2][2];
#pragma unroll
            for (int j = 0; j < 2; j++) {
                const int boff = 36864 + (wn + j * 8 + gq) * ROWB + ks * 32 + tq * 4;
                bgh[j][0] = *(const uint32_t*)(sb + boff);
                bgh[j][1] = *(const uint32_t*)(sb + boff + 16);
                bgl[j][0] = *(const uint32_t*)(sb + boff + 9216);
                bgl[j][1] = *(const uint32_t*)(sb + boff + 9216 + 16);
                buh[j][0] = *(const uint32_t*)(sb + boff + 18432);
                buh[j][1] = *(const uint32_t*)(sb + boff + 18432 + 16);
                bul[j][0] = *(const uint32_t*)(sb + boff + 27648);
                bul[j][1] = *(const uint32_t*)(sb + boff + 27648 + 16);
            }
#pragma unroll
            for (int i = 0; i < 4; i++)
#pragma unroll
                for (int j = 0; j < 2; j++) {
                    mma_bf16(accg[i][j], ah[i], bgh[j]);
                    mma_bf16(accg[i][j], ah[i], bgl[j]);
                    mma_bf16(accg[i][j], al[i], bgh[j]);
                    mma_bf16(accu[i][j], ah[i], buh[j]);
                    mma_bf16(accu[i][j], ah[i], bul[j]);
                    mma_bf16(accu[i][j], al[i], buh[j]);
                }
        }
        __syncthreads();
        if (s + 2 < NS) load_stage(s + 2, s & 1);
    }

    // epilogue: silu(gate)*up -> bf16 hi/lo direct to global
#pragma unroll
    for (int i = 0; i < 4; i++) {
        const int rg = row0 + wm + i * 16 + gq;
#pragma unroll
        for (int j = 0; j < 2; j++) {
            const int col = n0 + wn + j * 8 + 2 * tq;
#pragma unroll
            for (int h = 0; h < 2; h++) {
                const float g0 = accg[i][j][h * 2 + 0], g1 = accg[i][j][h * 2 + 1];
                const float u0 = accu[i][j][h * 2 + 0], u1 = accu[i][j][h * 2 + 1];
                const float v0 = u0 * g0 / (1.f + expf(-g0));
                const float v1 = u1 * g1 / (1.f + expf(-g1));
                const __nv_bfloat16 h0 = __float2bfloat16(v0);
                const __nv_bfloat16 h1 = __float2bfloat16(v1);
                const __nv_bfloat16 l0 = __float2bfloat16(v0 - __bfloat162float(h0));
                const __nv_bfloat16 l1 = __float2bfloat16(v1 - __bfloat162float(h1));
                const size_t o = ((size_t)e * CAP + rg + h * 8) * INTERN + col;
                *(uint32_t*)(g_inter_hi + o) = bpack(h0, h1);
                *(uint32_t*)(g_inter_lo + o) = bpack(l0, l1);
            }
        }
    }
}

// ---------------------------------------------------------------------------
// GEMM2: eo = inter @ down.  CTA tile M=128, N=128, BK=64. warp 64x32.
// SMEM stage: Ahi(0) Alo(18432) Bh(36864) Bl(55296)
// ---------------------------------------------------------------------------
__global__ __launch_bounds__(256) void gemm2_mma() {
    extern __shared__ char smem[];
    const int tid  = threadIdx.x;
    const int e    = blockIdx.z;
    const int row0 = blockIdx.y * 128;
    const int n0   = blockIdx.x * 128;
    const uint32_t sdyn = smem_u32(smem);

    auto load_stage = [&](int s, int buf) {
        const int k0 = s * 64;
        const uint32_t sd = sdyn + buf * ST_SZ;
#pragma unroll
        for (int i = 0; i < 8; i++) {
            const int idx = tid + i * 256, row = idx >> 4, cc = idx & 15;
            const size_t oa = ((size_t)e * CAP + row0 + row) * INTERN + k0 + cc * 4;
            const uint32_t d = sd + row * ROWB + cc * 8;
            cp8(d,         g_inter_hi + oa, 8);
            cp8(d + 18432, g_inter_lo + oa, 8);
        }
#pragma unroll
        for (int i = 0; i < 8; i++) {
            const int idx = tid + i * 256, row = idx >> 4, cc = idx & 15;
            const size_t ob = ((size_t)e * HID + n0 + row) * INTERN + k0 + cc * 4;
            const uint32_t d = sd + 36864 + row * ROWB + cc * 8;
            cp8(d,         g_dpT_hi + ob, 8);
            cp8(d + 18432, g_dpT_lo + ob, 8);
        }
        CP_COMMIT();
    };

    const int lane = tid & 31, wid = tid >> 5;
    const int wm = (wid & 1) * 64;
    const int wn = (wid >> 1) * 32;
    const int gq = lane >> 2, tq = lane & 3;

    float acc[4][4][4] = {};

    load_stage(0, 0);
    load_stage(1, 1);
    const int NS = INTERN / 64;  // 64
    for (int s = 0; s < NS; s++) {
        if (s < NS - 1) CP_WAIT1(); else CP_WAIT0();
        __syncthreads();
        const uint32_t sA = sdyn + (s & 1) * ST_SZ;
        const char*    sb = smem + (s & 1) * ST_SZ;
#pragma unroll
        for (int ks = 0; ks < 4; ks++) {
            uint32_t ah[4][4], al[4][4];
#pragma unroll
            for (int i = 0; i < 4; i++) {
                const uint32_t ad = sA + (wm + i * 16 + (lane & 15)) * ROWB
                                       + (ks * 16 + ((lane >> 4) << 3)) * 2;
                ldm4(ah[i], ad);
                ldm4(al[i], ad + 18432);
            }
            uint32_t bh[4][2], bl[4][2];
#pragma unroll
            for (int j = 0; j < 4; j++) {
                const int boff = 36864 + (wn + j * 8 + gq) * ROWB + ks * 32 + tq * 4;
                bh[j][0] = *(const uint32_t*)(sb + boff);
                bh[j][1] = *(const uint32_t*)(sb + boff + 16);
                bl[j][0] = *(const uint32_t*)(sb + boff + 18432);
                bl[j][1] = *(const uint32_t*)(sb + boff + 18432 + 16);
            }
#pragma unroll
            for (int i = 0; i < 4; i++)
#pragma unroll
                for (int j = 0; j < 4; j++) {
                    mma_bf16(acc[i][j], ah[i], bh[j]);
                    mma_bf16(acc[i][j], ah[i], bl[j]);
                    mma_bf16(acc[i][j], al[i], bh[j]);
                }
        }
        __syncthreads();
        if (s + 2 < NS) load_stage(s + 2, s & 1);
    }

#pragma unroll
    for (int i = 0; i < 4; i++) {
        const int rg = row0 + wm + i * 16 + gq;
#pragma unroll
        for (int j = 0; j < 4; j++) {
            const int col = n0 + wn + j * 8 + 2 * tq;
#pragma unroll
            for (int h = 0; h < 2; h++) {
                const size_t o = ((size_t)e * CAP + rg + h * 8) * HID + col;
                *(float2*)(g_eo + o) = make_float2(acc[i][j][h * 2], acc[i][j][h * 2 + 1]);
            }
        }
    }
}

// ---------------------------------------------------------------------------
// Combine (verified R1)
// ---------------------------------------------------------------------------
__global__ void combine_kernel(const float* __restrict__ aff,
                               const int*   __restrict__ eidx,
                               float*       __restrict__ out) {
    const int idx = blockIdx.x * 256 + threadIdx.x;
    const int t = idx >> 8;
    const int c = (idx & 255) << 2;
    const int2 ei = ((const int2*)eidx)[t];
    const float a0 = aff[t * NE + ei.x];
    const float a1 = aff[t * NE + ei.y];
    const float inv = 1.f / (a0 + a1);
    const int s0 = g_slot[t * TOPK + 0];
    const int s1 = g_slot[t * TOPK + 1];
    float4 r = make_float4(0.f, 0.f, 0.f, 0.f);
    if (s0 < ECAP) {
        const float w = a0 * inv;
        const float4 v = *(const float4*)(g_eo + (size_t)s0 * HID + c);
        r.x += w * v.x; r.y += w * v.y; r.z += w * v.z; r.w += w * v.w;
    }
    if (s1 < ECAP) {
        const float w = a1 * inv;
        const float4 v = *(const float4*)(g_eo + (size_t)s1 * HID + c);
        r.x += w * v.x; r.y += w * v.y; r.z += w * v.z; r.w += w * v.w;
    }
    *(float4*)(out + (size_t)t * HID + c) = r;
}

// ---------------------------------------------------------------------------
extern "C" void kernel_launch(void* const* d_in, const int* in_sizes, int n_in,
                              void* d_out, int out_size) {
    const float* x    = (const float*)d_in[0];
    const float* aff  = (const float*)d_in[1];
    const int*   eidx = (const int*)  d_in[2];
    const float* gup  = (const float*)d_in[3];
    const float* dp   = (const float*)d_in[4];
    float* out = (float*)d_out;

    cudaFuncSetAttribute(gemm1_mma, cudaFuncAttributeMaxDynamicSharedMemorySize, SM_SZ);
    cudaFuncSetAttribute(gemm2_mma, cudaFuncAttributeMaxDynamicSharedMemorySize, SM_SZ);

    routing_kernel<<<1, 256>>>(eidx);
    split_x<<<(TTOK * HID) / 1024, 256>>>(x);
    transpose_gup<<<dim3(2 * INTERN / 32, HID / 32, NE), 256>>>(gup);
    transpose_dp<<<dim3(HID / 32, INTERN / 32, NE), 256>>>(dp);
    gemm1_mma<<<dim3(INTERN / 64, CAP / 128, NE), 256, SM_SZ>>>();
    gemm2_mma<<<dim3(HID / 128, CAP / 128, NE), 256, SM_SZ>>>();
    combine_kernel<<<(TTOK * (HID / 4)) / 256, 256>>>(aff, eidx, out);
}

// round 4
// speedup vs baseline: 2.4694x; 1.0634x over previous
#include <cuda_runtime.h>
#include <cuda_bf16.h>
#include <math.h>
#include <stdint.h>

#define NE      8
#define TOPK    2
#define HID     1024
#define INTERN  4096
#define TTOK    8192
#define CAP     2560
#define ECAP    (NE*CAP)

// ---------------- scratch (static device globals) ----------------
__device__ int            g_src_token[ECAP];
__device__ int            g_slot[TTOK * TOPK];
__device__ int            g_count[NE];
__device__ __nv_bfloat16  g_xhi[(size_t)TTOK * HID];
__device__ __nv_bfloat16  g_xlo[(size_t)TTOK * HID];
__device__ __nv_bfloat16  g_gupT_hi[(size_t)NE * 2 * INTERN * HID];  // [e][n][k]
__device__ __nv_bfloat16  g_gupT_lo[(size_t)NE * 2 * INTERN * HID];
__device__ __nv_bfloat16  g_dpT_hi[(size_t)NE * HID * INTERN];       // [e][n][k]
__device__ __nv_bfloat16  g_dpT_lo[(size_t)NE * HID * INTERN];
__device__ __nv_bfloat16  g_inter_hi[(size_t)ECAP * INTERN];
__device__ __nv_bfloat16  g_inter_lo[(size_t)ECAP * INTERN];
__device__ float          g_eo[(size_t)ECAP * HID];

// ---------------- helpers ----------------
__device__ __forceinline__ uint32_t smem_u32(const void* p) {
    uint32_t a;
    asm("{ .reg .u64 t; cvta.to.shared.u64 t, %1; cvt.u32.u64 %0, t; }" : "=r"(a) : "l"(p));
    return a;
}
__device__ __forceinline__ void mma_bf16(float* d, const uint32_t* a, const uint32_t* b) {
    asm volatile(
        "mma.sync.aligned.m16n8k16.row.col.f32.bf16.bf16.f32 "
        "{%0,%1,%2,%3}, {%4,%5,%6,%7}, {%8,%9}, {%0,%1,%2,%3};"
        : "+f"(d[0]), "+f"(d[1]), "+f"(d[2]), "+f"(d[3])
        : "r"(a[0]), "r"(a[1]), "r"(a[2]), "r"(a[3]), "r"(b[0]), "r"(b[1]));
}
__device__ __forceinline__ void ldm4(uint32_t* r, uint32_t addr) {
    asm volatile("ldmatrix.sync.aligned.m8n8.x4.shared.b16 {%0,%1,%2,%3}, [%4];"
        : "=r"(r[0]), "=r"(r[1]), "=r"(r[2]), "=r"(r[3]) : "r"(addr));
}
__device__ __forceinline__ void cp8(uint32_t dst, const void* src, uint32_t sz) {
    asm volatile("cp.async.ca.shared.global [%0], [%1], 8, %2;"
        :: "r"(dst), "l"(src), "r"(sz) : "memory");
}
#define CP_COMMIT() asm volatile("cp.async.commit_group;" ::: "memory")
#define CP_WAIT2()  asm volatile("cp.async.wait_group 2;" ::: "memory")
#define CP_WAIT1()  asm volatile("cp.async.wait_group 1;" ::: "memory")
#define CP_WAIT0()  asm volatile("cp.async.wait_group 0;" ::: "memory")

__device__ __forceinline__ uint32_t bpack(__nv_bfloat16 a, __nv_bfloat16 b) {
    return (uint32_t)__bfloat16_as_ushort(a) | ((uint32_t)__bfloat16_as_ushort(b) << 16);
}

// SMEM geometry: rows padded to 72 bf16 (144B), conflict-free (verified R3).
#define ROWB   144
#define ST_SZ  73728             // bytes per pipeline stage
#define SM_SZ  (3 * ST_SZ)       // 221184 (3-stage pipeline)

// ---------------------------------------------------------------------------
// Routing + per-expert counts
// ---------------------------------------------------------------------------
__global__ void routing_kernel(const int* __restrict__ expert_index) {
    const int e    = threadIdx.x >> 5;
    const int lane = threadIdx.x & 31;
    int count = 0;
    for (int base = 0; base < TTOK; base += 32) {
        const int t = base + lane;
        const int2 ei = ((const int2*)expert_index)[t];
        int k = -1;
        if (ei.x == e) k = 0;
        else if (ei.y == e) k = 1;
        const unsigned m = __ballot_sync(0xffffffffu, k >= 0);
        if (k >= 0) {
            const int pos = count + __popc(m & ((1u << lane) - 1u));
            if (pos < CAP) {
                g_src_token[e * CAP + pos] = t;
                g_slot[t * TOPK + k] = e * CAP + pos;
            } else {
                g_slot[t * TOPK + k] = ECAP;
            }
        }
        count += __popc(m);
    }
    const int filled = count < CAP ? count : CAP;
    for (int p = filled + lane; p < CAP; p += 32)
        g_src_token[e * CAP + p] = -1;
    if (lane == 0) g_count[e] = filled;
}

// ---------------------------------------------------------------------------
// Prep: split hidden states to bf16 hi/lo
// ---------------------------------------------------------------------------
__global__ void split_x(const float* __restrict__ x) {
    const size_t i0 = ((size_t)blockIdx.x * 256 + threadIdx.x) * 4;
    const float4 v = *(const float4*)(x + i0);
    const float vv[4] = {v.x, v.y, v.z, v.w};
    uint32_t hp[2], lp[2];
#pragma unroll
    for (int j = 0; j < 2; j++) {
        __nv_bfloat16 h0 = __float2bfloat16(vv[2*j]);
        __nv_bfloat16 h1 = __float2bfloat16(vv[2*j+1]);
        __nv_bfloat16 l0 = __float2bfloat16(vv[2*j]   - __bfloat162float(h0));
        __nv_bfloat16 l1 = __float2bfloat16(vv[2*j+1] - __bfloat162float(h1));
        hp[j] = bpack(h0, h1);
        lp[j] = bpack(l0, l1);
    }
    *(uint2*)(g_xhi + i0) = make_uint2(hp[0], hp[1]);
    *(uint2*)(g_xlo + i0) = make_uint2(lp[0], lp[1]);
}

// ---------------------------------------------------------------------------
// Prep: transpose + bf16 hi/lo split:  in[e][R][C] -> out[e][C][R]
// ---------------------------------------------------------------------------
__device__ __forceinline__ void transpose_body(
        const float* __restrict__ in, __nv_bfloat16* __restrict__ ohi,
        __nv_bfloat16* __restrict__ olo, int R, int C) {
    __shared__ float tile[32][33];
    const int e  = blockIdx.z;
    const int r0 = blockIdx.y * 32, c0 = blockIdx.x * 32;
    const int tx = threadIdx.x & 31, ty = threadIdx.x >> 5;
    const size_t base = (size_t)e * R * C;
#pragma unroll
    for (int i = 0; i < 32; i += 8)
        tile[ty + i][tx] = in[base + (size_t)(r0 + ty + i) * C + c0 + tx];
    __syncthreads();
#pragma unroll
    for (int i = 0; i < 32; i += 8) {
        const float v = tile[tx][ty + i];
        const __nv_bfloat16 h = __float2bfloat16(v);
        const __nv_bfloat16 l = __float2bfloat16(v - __bfloat162float(h));
        const size_t o = base + (size_t)(c0 + ty + i) * R + r0 + tx;
        ohi[o] = h;
        olo[o] = l;
    }
}
__global__ void transpose_gup(const float* __restrict__ in) {
    transpose_body(in, g_gupT_hi, g_gupT_lo, HID, 2 * INTERN);
}
__global__ void transpose_dp(const float* __restrict__ in) {
    transpose_body(in, g_dpT_hi, g_dpT_lo, INTERN, HID);
}

// ---------------------------------------------------------------------------
// GEMM1: inter = silu(X@Wg)*(X@Wu), bf16 3-term split, mma.sync m16n8k16.
// CTA tile M=128, N=64(gate)+64(up), BK=64, 3-stage cp.async pipeline.
// SMEM stage: Ahi(0) Alo(18432) Bgh(36864) Bgl(46080) Buh(55296) Bul(64512)
// ---------------------------------------------------------------------------
__global__ __launch_bounds__(256) void gemm1_mma() {
    const int e    = blockIdx.z;
    const int row0 = blockIdx.y * 128;
    if (row0 >= g_count[e]) return;          // dead-tile elimination

    extern __shared__ char smem[];
    __shared__ int s_tok[128];
    const int tid = threadIdx.x;
    const int n0  = blockIdx.x * 64;

    if (tid < 128) s_tok[tid] = g_src_token[e * CAP + row0 + tid];
    __syncthreads();
    const uint32_t sdyn = smem_u32(smem);

    auto load_stage = [&](int s, int buf) {
        const int k0 = s * 64;
        const uint32_t sd = sdyn + buf * ST_SZ;
#pragma unroll
        for (int i = 0; i < 8; i++) {
            const int idx = tid + i * 256, row = idx >> 4, cc = idx & 15;
            const int tok = s_tok[row];
            const int tokc = tok < 0 ? 0 : tok;
            const uint32_t sz = tok < 0 ? 0u : 8u;
            const size_t so = (size_t)tokc * HID + k0 + cc * 4;
            const uint32_t d = sd + row * ROWB + cc * 8;
            cp8(d,         g_xhi + so, sz);
            cp8(d + 18432, g_xlo + so, sz);
        }
#pragma unroll
        for (int i = 0; i < 4; i++) {
            const int idx = tid + i * 256, row = idx >> 4, cc = idx & 15;
            const size_t og = ((size_t)e * 2 * INTERN + n0 + row) * HID + k0 + cc * 4;
            const size_t ou = og + (size_t)INTERN * HID;
            const uint32_t d = sd + 36864 + row * ROWB + cc * 8;
            cp8(d,         g_gupT_hi + og, 8);
            cp8(d + 9216,  g_gupT_lo + og, 8);
            cp8(d + 18432, g_gupT_hi + ou, 8);
            cp8(d + 27648, g_gupT_lo + ou, 8);
        }
        CP_COMMIT();
    };

    const int lane = tid & 31, wid = tid >> 5;
    const int wm = (wid & 1) * 64;
    const int wn = (wid >> 1) * 16;
    const int gq = lane >> 2, tq = lane & 3;

    float accg[4][2][4] = {}, accu[4][2][4] = {};

    const int NS = HID / 64;  // 16
    load_stage(0, 0);
    load_stage(1, 1);
    load_stage(2, 2);
    int buf = 0;
    for (int s = 0; s < NS; s++) {
        if (s + 3 <= NS) CP_WAIT2();
        else if (s + 2 == NS) CP_WAIT1();
        else CP_WAIT0();
        __syncthreads();
        const uint32_t sA = sdyn + buf * ST_SZ;
        const char*    sb = smem + buf * ST_SZ;
#pragma unroll
        for (int ks = 0; ks < 4; ks++) {
            uint32_t ah[4][4], al[4][4];
#pragma unroll
            for (int i = 0; i < 4; i++) {
                const uint32_t ad = sA + (wm + i * 16 + (lane & 15)) * ROWB
                                       + (ks * 16 + ((lane >> 4) << 3)) * 2;
                ldm4(ah[i], ad);
                ldm4(al[i], ad + 18432);
            }
            uint32_t bgh[2][2], bgl[2][2], buh[2][2], bul[2][2];
#pragma unroll
            for (int j = 0; j < 2; j++) {
                const int boff = 36864 + (wn + j * 8 + gq) * ROWB + ks * 32 + tq * 4;
                bgh[j][0] = *(const uint32_t*)(sb + boff);
                bgh[j][1] = *(const uint32_t*)(sb + boff + 16);
                bgl[j][0] = *(const uint32_t*)(sb + boff + 9216);
                bgl[j][1] = *(const uint32_t*)(sb + boff + 9216 + 16);
                buh[j][0] = *(const uint32_t*)(sb + boff + 18432);
                buh[j][1] = *(const uint32_t*)(sb + boff + 18432 + 16);
                bul[j][0] = *(const uint32_t*)(sb + boff + 27648);
                bul[j][1] = *(const uint32_t*)(sb + boff + 27648 + 16);
            }
#pragma unroll
            for (int i = 0; i < 4; i++)
#pragma unroll
                for (int j = 0; j < 2; j++) {
                    mma_bf16(accg[i][j], ah[i], bgh[j]);
                    mma_bf16(accg[i][j], ah[i], bgl[j]);
                    mma_bf16(accg[i][j], al[i], bgh[j]);
                    mma_bf16(accu[i][j], ah[i], buh[j]);
                    mma_bf16(accu[i][j], ah[i], bul[j]);
                    mma_bf16(accu[i][j], al[i], buh[j]);
                }
        }
        __syncthreads();
        if (s + 3 < NS) load_stage(s + 3, buf);
        buf = (buf == 2) ? 0 : buf + 1;
    }

    // epilogue: silu(gate)*up -> bf16 hi/lo direct to global
#pragma unroll
    for (int i = 0; i < 4; i++) {
        const int rg = row0 + wm + i * 16 + gq;
#pragma unroll
        for (int j = 0; j < 2; j++) {
            const int col = n0 + wn + j * 8 + 2 * tq;
#pragma unroll
            for (int h = 0; h < 2; h++) {
                const float g0 = accg[i][j][h * 2 + 0], g1 = accg[i][j][h * 2 + 1];
                const float u0 = accu[i][j][h * 2 + 0], u1 = accu[i][j][h * 2 + 1];
                const float v0 = u0 * g0 / (1.f + __expf(-g0));
                const float v1 = u1 * g1 / (1.f + __expf(-g1));
                const __nv_bfloat16 h0 = __float2bfloat16(v0);
                const __nv_bfloat16 h1 = __float2bfloat16(v1);
                const __nv_bfloat16 l0 = __float2bfloat16(v0 - __bfloat162float(h0));
                const __nv_bfloat16 l1 = __float2bfloat16(v1 - __bfloat162float(h1));
                const size_t o = ((size_t)e * CAP + rg + h * 8) * INTERN + col;
                *(uint32_t*)(g_inter_hi + o) = bpack(h0, h1);
                *(uint32_t*)(g_inter_lo + o) = bpack(l0, l1);
            }
        }
    }
}

// ---------------------------------------------------------------------------
// GEMM2: eo = inter @ down.  CTA tile M=128, N=128, BK=64, 3-stage pipeline.
// SMEM stage: Ahi(0) Alo(18432) Bh(36864) Bl(55296)
// ---------------------------------------------------------------------------
__global__ __launch_bounds__(256) void gemm2_mma() {
    const int e    = blockIdx.z;
    const int row0 = blockIdx.y * 128;
    if (row0 >= g_count[e]) return;          // dead-tile elimination

    extern __shared__ char smem[];
    const int tid = threadIdx.x;
    const int n0  = blockIdx.x * 128;
    const uint32_t sdyn = smem_u32(smem);

    auto load_stage = [&](int s, int buf) {
        const int k0 = s * 64;
        const uint32_t sd = sdyn + buf * ST_SZ;
#pragma unroll
        for (int i = 0; i < 8; i++) {
            const int idx = tid + i * 256, row = idx >> 4, cc = idx & 15;
            const size_t oa = ((size_t)e * CAP + row0 + row) * INTERN + k0 + cc * 4;
            const uint32_t d = sd + row * ROWB + cc * 8;
            cp8(d,         g_inter_hi + oa, 8);
            cp8(d + 18432, g_inter_lo + oa, 8);
        }
#pragma unroll
        for (int i = 0; i < 8; i++) {
            const int idx = tid + i * 256, row = idx >> 4, cc = idx & 15;
            const size_t ob = ((size_t)e * HID + n0 + row) * INTERN + k0 + cc * 4;
            const uint32_t d = sd + 36864 + row * ROWB + cc * 8;
            cp8(d,         g_dpT_hi + ob, 8);
            cp8(d + 18432, g_dpT_lo + ob, 8);
        }
        CP_COMMIT();
    };

    const int lane = tid & 31, wid = tid >> 5;
    const int wm = (wid & 1) * 64;
    const int wn = (wid >> 1) * 32;
    const int gq = lane >> 2, tq = lane & 3;

    float acc[4][4][4] = {};

    const int NS = INTERN / 64;  // 64
    load_stage(0, 0);
    load_stage(1, 1);
    load_stage(2, 2);
    int buf = 0;
    for (int s = 0; s < NS; s++) {
        if (s + 3 <= NS) CP_WAIT2();
        else if (s + 2 == NS) CP_WAIT1();
        else CP_WAIT0();
        __syncthreads();
        const uint32_t sA = sdyn + buf * ST_SZ;
        const char*    sb = smem + buf * ST_SZ;
#pragma unroll
        for (int ks = 0; ks < 4; ks++) {
            uint32_t ah[4][4], al[4][4];
#pragma unroll
            for (int i = 0; i < 4; i++) {
                const uint32_t ad = sA + (wm + i * 16 + (lane & 15)) * ROWB
                                       + (ks * 16 + ((lane >> 4) << 3)) * 2;
                ldm4(ah[i], ad);
                ldm4(al[i], ad + 18432);
            }
            uint32_t bh[4][2], bl[4][2];
#pragma unroll
            for (int j = 0; j < 4; j++) {
                const int boff = 36864 + (wn + j * 8 + gq) * ROWB + ks * 32 + tq * 4;
                bh[j][0] = *(const uint32_t*)(sb + boff);
                bh[j][1] = *(const uint32_t*)(sb + boff + 16);
                bl[j][0] = *(const uint32_t*)(sb + boff + 18432);
                bl[j][1] = *(const uint32_t*)(sb + boff + 18432 + 16);
            }
#pragma unroll
            for (int i = 0; i < 4; i++)
#pragma unroll
                for (int j = 0; j < 4; j++) {
                    mma_bf16(acc[i][j], ah[i], bh[j]);
                    mma_bf16(acc[i][j], ah[i], bl[j]);
                    mma_bf16(acc[i][j], al[i], bh[j]);
                }
        }
        __syncthreads();
        if (s + 3 < NS) load_stage(s + 3, buf);
        buf = (buf == 2) ? 0 : buf + 1;
    }

#pragma unroll
    for (int i = 0; i < 4; i++) {
        const int rg = row0 + wm + i * 16 + gq;
#pragma unroll
        for (int j = 0; j < 4; j++) {
            const int col = n0 + wn + j * 8 + 2 * tq;
#pragma unroll
            for (int h = 0; h < 2; h++) {
                const size_t o = ((size_t)e * CAP + rg + h * 8) * HID + col;
                *(float2*)(g_eo + o) = make_float2(acc[i][j][h * 2], acc[i][j][h * 2 + 1]);
            }
        }
    }
}

// ---------------------------------------------------------------------------
// Combine (verified R1)
// ---------------------------------------------------------------------------
__global__ void combine_kernel(const float* __restrict__ aff,
                               const int*   __restrict__ eidx,
                               float*       __restrict__ out) {
    const int idx = blockIdx.x * 256 + threadIdx.x;
    const int t = idx >> 8;
    const int c = (idx & 255) << 2;
    const int2 ei = ((const int2*)eidx)[t];
    const float a0 = aff[t * NE + ei.x];
    const float a1 = aff[t * NE + ei.y];
    const float inv = 1.f / (a0 + a1);
    const int s0 = g_slot[t * TOPK + 0];
    const int s1 = g_slot[t * TOPK + 1];
    float4 r = make_float4(0.f, 0.f, 0.f, 0.f);
    if (s0 < ECAP) {
        const float w = a0 * inv;
        const float4 v = *(const float4*)(g_eo + (size_t)s0 * HID + c);
        r.x += w * v.x; r.y += w * v.y; r.z += w * v.z; r.w += w * v.w;
    }
    if (s1 < ECAP) {
        const float w = a1 * inv;
        const float4 v = *(const float4*)(g_eo + (size_t)s1 * HID + c);
        r.x += w * v.x; r.y += w * v.y; r.z += w * v.z; r.w += w * v.w;
    }
    *(float4*)(out + (size_t)t * HID + c) = r;
}

// ---------------------------------------------------------------------------
extern "C" void kernel_launch(void* const* d_in, const int* in_sizes, int n_in,
                              void* d_out, int out_size) {
    const float* x    = (const float*)d_in[0];
    const float* aff  = (const float*)d_in[1];
    const int*   eidx = (const int*)  d_in[2];
    const float* gup  = (const float*)d_in[3];
    const float* dp   = (const float*)d_in[4];
    float* out = (float*)d_out;

    cudaFuncSetAttribute(gemm1_mma, cudaFuncAttributeMaxDynamicSharedMemorySize, SM_SZ);
    cudaFuncSetAttribute(gemm2_mma, cudaFuncAttributeMaxDynamicSharedMemorySize, SM_SZ);

    routing_kernel<<<1, 256>>>(eidx);
    split_x<<<(TTOK * HID) / 1024, 256>>>(x);
    transpose_gup<<<dim3(2 * INTERN / 32, HID / 32, NE), 256>>>(gup);
    transpose_dp<<<dim3(HID / 32, INTERN / 32, NE), 256>>>(dp);
    gemm1_mma<<<dim3(INTERN / 64, CAP / 128, NE), 256, SM_SZ>>>();
    gemm2_mma<<<dim3(HID / 128, CAP / 128, NE), 256, SM_SZ>>>();
    combine_kernel<<<(TTOK * (HID / 4)) / 256, 256>>>(aff, eidx, out);
}